// round 7
// baseline (speedup 1.0000x reference)
#include <cuda_runtime.h>
#include <cstdint>

// Problem constants: x (8,512,64,64) f32, mask (64,64) i32, out (8,768,64,64) f32
#define HW      4096
#define BATCH   8
#define CIN     512
#define C2      256
#define COUT    768

// Scratch (allocation-free rule: __device__ globals)
__device__ int g_cols[HW];   // ascending list of unmasked (flag=false) columns
__device__ int g_m;          // count of unmasked columns
__device__ int g_sidx[HW];   // flag[i] ? nb[i] : -1

// ---------------------------------------------------------------------------
// threefry2x32 with key (0, 42), counters (x0=0, x1=c). JAX partitionable path:
// bits[i] = o0 ^ o1 with counter = i. ks = [0, 42, 0 ^ 42 ^ 0x1BD11BDA].
// Returns the 23-bit monotone proxy for uniform(float) directly.
// ---------------------------------------------------------------------------
__device__ __forceinline__ unsigned threefry_bits(unsigned c) {
    const unsigned ks1 = 42u;
    const unsigned ks2 = 0x1BD11BDAu ^ 42u;   // 0x1BD11BF0
    unsigned x0 = 0u;          // counts_hi + ks0
    unsigned x1 = c + ks1;     // counts_lo + ks1
#define TF_RND(r) { x0 += x1; x1 = __funnelshift_l(x1, x1, (r)); x1 ^= x0; }
    TF_RND(13) TF_RND(15) TF_RND(26) TF_RND(6)
    x0 += ks1;  x1 += ks2 + 1u;
    TF_RND(17) TF_RND(29) TF_RND(16) TF_RND(24)
    x0 += ks2;  x1 += 0u  + 2u;
    TF_RND(13) TF_RND(15) TF_RND(26) TF_RND(6)
    x0 += 0u;   x1 += ks1 + 3u;
    TF_RND(17) TF_RND(29) TF_RND(16) TF_RND(24)
    x0 += ks1;  x1 += ks2 + 4u;
    TF_RND(13) TF_RND(15) TF_RND(26) TF_RND(6)
    x0 += ks2;  x1 += 0u  + 5u;
#undef TF_RND
    return (x0 ^ x1) >> 9;
}

// ---------------------------------------------------------------------------
// Kernel A: ordered compaction of unmasked column indices. 1 block, 1024 thr.
// Warp-shuffle scans; 3 barriers total.
// ---------------------------------------------------------------------------
__global__ void __launch_bounds__(1024) compact_kernel(const int* __restrict__ mask) {
    __shared__ int wtot[32];
    const int tid  = threadIdx.x;
    const int lane = tid & 31;
    const int warp = tid >> 5;
    const int base = tid * 4;

    int f[4]; int cnt = 0;
#pragma unroll
    for (int k = 0; k < 4; k++) { f[k] = (mask[base + k] <= 0) ? 1 : 0; cnt += f[k]; }

    // warp inclusive scan of per-thread counts
    int inc = cnt;
#pragma unroll
    for (int o = 1; o < 32; o <<= 1) {
        int v = __shfl_up_sync(0xFFFFFFFFu, inc, o);
        if (lane >= o) inc += v;
    }
    if (lane == 31) wtot[warp] = inc;
    __syncthreads();
    if (warp == 0) {
        int v = wtot[lane];
#pragma unroll
        for (int o = 1; o < 32; o <<= 1) {
            int u = __shfl_up_sync(0xFFFFFFFFu, v, o);
            if (lane >= o) v += u;
        }
        wtot[lane] = v;
        if (lane == 31) g_m = v;
    }
    __syncthreads();

    int pos = inc - cnt + (warp ? wtot[warp - 1] : 0);  // exclusive global prefix
#pragma unroll
    for (int k = 0; k < 4; k++) {
        if (f[k]) g_cols[pos++] = base + k;
    }
}

// ---------------------------------------------------------------------------
// Kernel B: per-row masked argmax of the fixed uniform(key 42) matrix, fused
// with the flag fold. Rows with flag=false (mask<=0) never have their nb
// consumed -> write -1 and exit (halves the threefry work).
// One CTA per live row; column list staged in smem; ascending stride preserves
// first-occurrence tie-break within a thread; cross-thread ties resolved by
// the packed (val<<12)|(4095-j) key (max over key == min index among ties).
// ---------------------------------------------------------------------------
__global__ void __launch_bounds__(256) argmax_kernel(const int* __restrict__ mask) {
    const int row = blockIdx.x;
    const bool live = (mask[row] > 0);   // CTA-uniform
    if (!live) {                         // flag false: shift[...,row] = 0 anyway
        if (threadIdx.x == 0) g_sidx[row] = -1;
        return;                          // whole CTA exits together
    }

    __shared__ int scols[HW];
    __shared__ unsigned long long wmax[8];

    const int m = g_m;
    for (int t = threadIdx.x; t < m; t += 256) scols[t] = g_cols[t];
    __syncthreads();

    const unsigned rowbase = (unsigned)row * (unsigned)HW;

    unsigned bv = 0u;
    int bj = HW - 1;   // phantom (val=0, j=4095): loses to every real candidate

    int t = threadIdx.x;
    // unroll-by-2: two independent threefry chains in flight
    for (; t + 256 < m; t += 512) {
        int j0 = scols[t];
        int j1 = scols[t + 256];
        unsigned v0 = threefry_bits(rowbase + (unsigned)j0);
        unsigned v1 = threefry_bits(rowbase + (unsigned)j1);
        if (v0 > bv) { bv = v0; bj = j0; }      // j0 < j1: check in order
        if (v1 > bv) { bv = v1; bj = j1; }
    }
    if (t < m) {
        int j = scols[t];
        unsigned v = threefry_bits(rowbase + (unsigned)j);
        if (v > bv) { bv = v; bj = j; }
    }

    // intra-warp max of packed key via shuffles
    unsigned long long key =
        ((unsigned long long)bv << 12) | (unsigned)(HW - 1 - bj);
#pragma unroll
    for (int o = 16; o > 0; o >>= 1) {
        unsigned long long other = __shfl_xor_sync(0xFFFFFFFFu, key, o);
        if (other > key) key = other;
    }
    const int lane = threadIdx.x & 31;
    const int warp = threadIdx.x >> 5;
    if (lane == 0) wmax[warp] = key;
    __syncthreads();
    if (threadIdx.x < 32) {
        unsigned long long k2 = (threadIdx.x < 8) ? wmax[threadIdx.x] : 0ull;
#pragma unroll
        for (int o = 4; o > 0; o >>= 1) {
            unsigned long long other = __shfl_xor_sync(0xFFFFFFFFu, k2, o);
            if (other > k2) k2 = other;
        }
        if (threadIdx.x == 0)
            g_sidx[row] = (m == 0) ? 0 : (HW - 1 - (int)(k2 & 0xFFFu));
    }
}

// ---------------------------------------------------------------------------
// Kernel C: build the output. Plane p = b*768 + ch; ch<512 → straight copy,
// ch>=512 → masked gather from x channel (ch-256). sidx<0 → write zero.
// ---------------------------------------------------------------------------
__global__ void __launch_bounds__(256) output_kernel(const float* __restrict__ x,
                                                     float* __restrict__ out) {
    const int plane = blockIdx.x;              // 0 .. 8*768-1
    const int b  = plane / COUT;
    const int ch = plane - b * COUT;
    float4* __restrict__ dst = (float4*)(out + (size_t)plane * HW);

    if (ch < CIN) {
        const float4* __restrict__ src =
            (const float4*)(x + ((size_t)b * CIN + ch) * HW);
#pragma unroll
        for (int k = 0; k < 4; k++) {
            int idx = threadIdx.x + k * 256;
            dst[idx] = src[idx];
        }
    } else {
        const float* __restrict__ src = x + ((size_t)b * CIN + (ch - C2)) * HW;
        const int4* __restrict__ sidx4 = (const int4*)g_sidx;
#pragma unroll
        for (int k = 0; k < 4; k++) {
            int idx = threadIdx.x + k * 256;
            int4 s = sidx4[idx];
            float4 v;
            v.x = (s.x >= 0) ? src[s.x] : 0.0f;
            v.y = (s.y >= 0) ? src[s.y] : 0.0f;
            v.z = (s.z >= 0) ? src[s.z] : 0.0f;
            v.w = (s.w >= 0) ? src[s.w] : 0.0f;
            dst[idx] = v;
        }
    }
}

// ---------------------------------------------------------------------------
extern "C" void kernel_launch(void* const* d_in, const int* in_sizes, int n_in,
                              void* d_out, int out_size) {
    const float* x    = (const float*)d_in[0];   // (8,512,64,64) f32
    const int*   mask = (const int*)d_in[1];     // (64,64) i32
    float* out = (float*)d_out;                  // (8,768,64,64) f32
    (void)in_sizes; (void)n_in; (void)out_size;

    compact_kernel<<<1, 1024>>>(mask);
    argmax_kernel<<<HW, 256>>>(mask);
    output_kernel<<<BATCH * COUT, 256>>>(x, out);
}

// round 8
// speedup vs baseline: 1.2890x; 1.2890x over previous
#include <cuda_runtime.h>
#include <cstdint>

// Problem: x (8,512,64,64) f32, mask (64,64) i32, out (8,768,64,64) f32
#define HW      4096
#define BATCH   8
#define CIN     512
#define C2      256
#define COUT    768

#define N_ARG   HW                 // 4096 argmax CTAs (one per row)
#define N_COPY  (BATCH * CIN)      // 4096 copy planes
#define N_SHIFT (BATCH * C2)       // 2048 shift planes
#define GRID_TOTAL (N_ARG + N_COPY + N_SHIFT)

// Scratch (allocation-free rule: __device__ globals)
__device__ int g_sidx[HW];         // flag[i] ? nb[i] : -1
__device__ int g_done    = 0;      // argmax CTAs completed
__device__ int g_arrived = 0;      // shift CTAs past the spin

// ---------------------------------------------------------------------------
// threefry2x32 with key (0, 42), counters (x0=0, x1=c). JAX partitionable path:
// bits[i] = o0 ^ o1 with counter = i. ks = [0, 42, 0 ^ 42 ^ 0x1BD11BDA].
// Returns the 23-bit monotone proxy for uniform(float).
// ---------------------------------------------------------------------------
__device__ __forceinline__ unsigned threefry_bits(unsigned c) {
    const unsigned ks1 = 42u;
    const unsigned ks2 = 0x1BD11BDAu ^ 42u;   // 0x1BD11BF0
    unsigned x0 = 0u;          // counts_hi + ks0
    unsigned x1 = c + ks1;     // counts_lo + ks1
#define TF_RND(r) { x0 += x1; x1 = __funnelshift_l(x1, x1, (r)); x1 ^= x0; }
    TF_RND(13) TF_RND(15) TF_RND(26) TF_RND(6)
    x0 += ks1;  x1 += ks2 + 1u;
    TF_RND(17) TF_RND(29) TF_RND(16) TF_RND(24)
    x0 += ks2;  x1 += 0u  + 2u;
    TF_RND(13) TF_RND(15) TF_RND(26) TF_RND(6)
    x0 += 0u;   x1 += ks1 + 3u;
    TF_RND(17) TF_RND(29) TF_RND(16) TF_RND(24)
    x0 += ks1;  x1 += ks2 + 4u;
    TF_RND(13) TF_RND(15) TF_RND(26) TF_RND(6)
    x0 += ks2;  x1 += 0u  + 5u;
#undef TF_RND
    return (x0 ^ x1) >> 9;
}

// ---------------------------------------------------------------------------
// Single fused kernel.
//   bid <  4096           : argmax for row=bid (with per-CTA mask compaction)
//   4096 <= bid < 8192    : copy plane (out channels 0..511)
//   8192 <= bid           : shift plane (out channels 512..767), spin on g_done
// ---------------------------------------------------------------------------
__global__ void __launch_bounds__(256) fused_kernel(const float* __restrict__ x,
                                                    const int*   __restrict__ mask,
                                                    float*       __restrict__ out) {
    const int bid = blockIdx.x;
    const int tid = threadIdx.x;

    __shared__ int scols[HW];      // compacted unmasked columns (ascending)
    __shared__ int wred[8];
    __shared__ unsigned long long wmax[8];

    if (bid < N_ARG) {
        // ================= argmax CTA =================
        const int row = bid;
        if (mask[row] > 0) {
            // ---- per-CTA ordered compaction: thread t owns cols [16t,16t+16) ----
            const int lane = tid & 31;
            const int warp = tid >> 5;
            const int base = tid * 16;
            unsigned flags = 0;
            const int4* m4 = (const int4*)mask;
#pragma unroll
            for (int k = 0; k < 4; k++) {
                int4 v = m4[tid * 4 + k];
                if (v.x <= 0) flags |= 1u << (k * 4 + 0);
                if (v.y <= 0) flags |= 1u << (k * 4 + 1);
                if (v.z <= 0) flags |= 1u << (k * 4 + 2);
                if (v.w <= 0) flags |= 1u << (k * 4 + 3);
            }
            const int cnt = __popc(flags);
            int inc = cnt;
#pragma unroll
            for (int o = 1; o < 32; o <<= 1) {
                int v = __shfl_up_sync(0xFFFFFFFFu, inc, o);
                if (lane >= o) inc += v;
            }
            if (lane == 31) wred[warp] = inc;
            __syncthreads();
            if (tid < 32) {
                int v = (tid < 8) ? wred[tid] : 0;
#pragma unroll
                for (int o = 1; o < 8; o <<= 1) {
                    int u = __shfl_up_sync(0xFFFFFFFFu, v, o);
                    if (lane >= o) v += u;
                }
                if (tid < 8) wred[tid] = v;   // inclusive warp totals
            }
            __syncthreads();
            int pos = inc - cnt + (warp ? wred[warp - 1] : 0);
            const int m = wred[7];
#pragma unroll
            for (int k = 0; k < 16; k++) {
                if (flags & (1u << k)) scols[pos++] = base + k;
            }
            __syncthreads();

            // ---- masked argmax over compacted columns ----
            const unsigned rowbase = (unsigned)row * (unsigned)HW;
            unsigned bv = 0u;
            int bj = HW - 1;   // phantom (val=0, j=4095): loses to every real one

            int t = tid;
            for (; t + 256 < m; t += 512) {      // two independent chains
                int j0 = scols[t];
                int j1 = scols[t + 256];
                unsigned v0 = threefry_bits(rowbase + (unsigned)j0);
                unsigned v1 = threefry_bits(rowbase + (unsigned)j1);
                if (v0 > bv) { bv = v0; bj = j0; }   // j0 < j1: order preserved
                if (v1 > bv) { bv = v1; bj = j1; }
            }
            if (t < m) {
                int j = scols[t];
                unsigned v = threefry_bits(rowbase + (unsigned)j);
                if (v > bv) { bv = v; bj = j; }
            }

            unsigned long long key =
                ((unsigned long long)bv << 12) | (unsigned)(HW - 1 - bj);
#pragma unroll
            for (int o = 16; o > 0; o >>= 1) {
                unsigned long long other = __shfl_xor_sync(0xFFFFFFFFu, key, o);
                if (other > key) key = other;
            }
            if ((tid & 31) == 0) wmax[tid >> 5] = key;
            __syncthreads();
            if (tid < 32) {
                unsigned long long k2 = (tid < 8) ? wmax[tid] : 0ull;
#pragma unroll
                for (int o = 4; o > 0; o >>= 1) {
                    unsigned long long other = __shfl_xor_sync(0xFFFFFFFFu, k2, o);
                    if (other > k2) k2 = other;
                }
                if (tid == 0) {
                    g_sidx[row] = (m == 0) ? 0 : (HW - 1 - (int)(k2 & 0xFFFu));
                    __threadfence();
                    atomicAdd(&g_done, 1);
                }
            }
        } else {
            // dead row: nb never consumed
            if (tid == 0) {
                g_sidx[row] = -1;
                __threadfence();
                atomicAdd(&g_done, 1);
            }
        }
    } else if (bid < N_ARG + N_COPY) {
        // ================= copy CTA =================
        const int plane = bid - N_ARG;         // 0..4095
        const int b  = plane >> 9;             // /512
        const int ch = plane & 511;
        const float4* __restrict__ src =
            (const float4*)(x + ((size_t)b * CIN + ch) * HW);
        float4* __restrict__ dst =
            (float4*)(out + ((size_t)b * COUT + ch) * HW);
#pragma unroll
        for (int k = 0; k < 4; k++) {
            int idx = tid + k * 256;
            dst[idx] = src[idx];
        }
    } else {
        // ================= shift CTA =================
        const int p  = bid - N_ARG - N_COPY;   // 0..2047
        const int b  = p >> 8;
        const int cc = p & 255;

        if (tid == 0) {
            // spin until every argmax CTA has published; dispatch order
            // guarantees they started (and in practice finished) long ago.
            while (atomicAdd(&g_done, 0) != N_ARG) __nanosleep(200);
            // arrival protocol: the LAST CTA to pass the spin resets the
            // counters for the next graph replay (everyone else has already
            // observed g_done==N_ARG, so the reset cannot strand a spinner).
            int a = atomicAdd(&g_arrived, 1);
            if (a == N_SHIFT - 1) {
                atomicExch(&g_done, 0);
                atomicExch(&g_arrived, 0);
            }
        }
        __syncthreads();

        const float* __restrict__ src = x + ((size_t)b * CIN + C2 + cc) * HW;
        float4* __restrict__ dst =
            (float4*)(out + ((size_t)b * COUT + CIN + cc) * HW);
        const int4* __restrict__ sidx4 = (const int4*)g_sidx;
#pragma unroll
        for (int k = 0; k < 4; k++) {
            int idx = tid + k * 256;
            int4 s = sidx4[idx];
            float4 v;
            v.x = (s.x >= 0) ? __ldg(src + s.x) : 0.0f;
            v.y = (s.y >= 0) ? __ldg(src + s.y) : 0.0f;
            v.z = (s.z >= 0) ? __ldg(src + s.z) : 0.0f;
            v.w = (s.w >= 0) ? __ldg(src + s.w) : 0.0f;
            dst[idx] = v;
        }
    }
}

// ---------------------------------------------------------------------------
extern "C" void kernel_launch(void* const* d_in, const int* in_sizes, int n_in,
                              void* d_out, int out_size) {
    const float* x    = (const float*)d_in[0];   // (8,512,64,64) f32
    const int*   mask = (const int*)d_in[1];     // (64,64) i32
    float* out = (float*)d_out;                  // (8,768,64,64) f32
    (void)in_sizes; (void)n_in; (void)out_size;

    fused_kernel<<<GRID_TOTAL, 256>>>(x, mask, out);
}

// round 10
// speedup vs baseline: 1.4036x; 1.0889x over previous
#include <cuda_runtime.h>
#include <cstdint>

// Problem: x (8,512,64,64) f32, mask (64,64) i32, out (8,768,64,64) f32
#define HW      4096
#define BATCH   8
#define CIN     512
#define C2      256
#define COUT    768

#define N_MERGED HW                // 4096 CTAs: argmax row=bid + copy plane=bid
#define N_SHIFT  (BATCH * C2)      // 2048 shift planes
#define GRID_TOTAL (N_MERGED + N_SHIFT)

// Scratch (allocation-free rule: __device__ globals)
__device__ int g_sidx[HW];         // flag[i] ? nb[i] : -1
__device__ int g_done    = 0;      // merged CTAs that published their row
__device__ int g_arrived = 0;      // shift CTAs past the spin

// ---------------------------------------------------------------------------
// threefry2x32 with key (0, 42), counters (x0=0, x1=c). JAX partitionable path:
// bits[i] = o0 ^ o1 with counter = i. ks = [0, 42, 0 ^ 42 ^ 0x1BD11BDA].
// Returns the 23-bit monotone proxy for uniform(float).
// ---------------------------------------------------------------------------
__device__ __forceinline__ unsigned threefry_bits(unsigned c) {
    const unsigned ks1 = 42u;
    const unsigned ks2 = 0x1BD11BDAu ^ 42u;   // 0x1BD11BF0
    unsigned x0 = 0u;          // counts_hi + ks0
    unsigned x1 = c + ks1;     // counts_lo + ks1
#define TF_RND(r) { x0 += x1; x1 = __funnelshift_l(x1, x1, (r)); x1 ^= x0; }
    TF_RND(13) TF_RND(15) TF_RND(26) TF_RND(6)
    x0 += ks1;  x1 += ks2 + 1u;
    TF_RND(17) TF_RND(29) TF_RND(16) TF_RND(24)
    x0 += ks2;  x1 += 0u  + 2u;
    TF_RND(13) TF_RND(15) TF_RND(26) TF_RND(6)
    x0 += 0u;   x1 += ks1 + 3u;
    TF_RND(17) TF_RND(29) TF_RND(16) TF_RND(24)
    x0 += ks1;  x1 += ks2 + 4u;
    TF_RND(13) TF_RND(15) TF_RND(26) TF_RND(6)
    x0 += ks2;  x1 += 0u  + 5u;
#undef TF_RND
    return (x0 ^ x1) >> 9;
}

// ---------------------------------------------------------------------------
// Single fused kernel.
//   bid < 4096 : argmax for row=bid (publish early), THEN copy plane=bid.
//                ALU-bound argmax warps overlap with memory-bound copy warps
//                across CTAs on the same SM.
//   bid >= 4096: shift plane; spin on g_done (dispatch order guarantees all
//                merged CTAs were scheduled first).
// ---------------------------------------------------------------------------
__global__ void __launch_bounds__(256) fused_kernel(const float* __restrict__ x,
                                                    const int*   __restrict__ mask,
                                                    float*       __restrict__ out) {
    const int bid = blockIdx.x;
    const int tid = threadIdx.x;

    if (bid < N_MERGED) {
        __shared__ unsigned scnt[HW];  // rowbase + compacted column (ascending)
        __shared__ int wred[8];
        __shared__ unsigned long long wmax[8];

        // ================= phase 1: argmax for row = bid =================
        const int row = bid;
        const unsigned rowbase = (unsigned)row * (unsigned)HW;
        if (mask[row] > 0) {
            // ---- per-CTA ordered compaction: thread t owns cols [16t,16t+16) ----
            const int lane = tid & 31;
            const int warp = tid >> 5;
            const unsigned base = rowbase + (unsigned)(tid * 16);
            unsigned flags = 0;
            const int4* m4 = (const int4*)mask;
#pragma unroll
            for (int k = 0; k < 4; k++) {
                int4 v = m4[tid * 4 + k];
                if (v.x <= 0) flags |= 1u << (k * 4 + 0);
                if (v.y <= 0) flags |= 1u << (k * 4 + 1);
                if (v.z <= 0) flags |= 1u << (k * 4 + 2);
                if (v.w <= 0) flags |= 1u << (k * 4 + 3);
            }
            const int cnt = __popc(flags);
            int inc = cnt;
#pragma unroll
            for (int o = 1; o < 32; o <<= 1) {
                int v = __shfl_up_sync(0xFFFFFFFFu, inc, o);
                if (lane >= o) inc += v;
            }
            if (lane == 31) wred[warp] = inc;
            __syncthreads();
            if (tid < 32) {
                int v = (tid < 8) ? wred[tid] : 0;
#pragma unroll
                for (int o = 1; o < 8; o <<= 1) {
                    int u = __shfl_up_sync(0xFFFFFFFFu, v, o);
                    if (lane >= o) v += u;
                }
                if (tid < 8) wred[tid] = v;   // inclusive warp totals
            }
            __syncthreads();
            int pos = inc - cnt + (warp ? wred[warp - 1] : 0);
            const int m = wred[7];
#pragma unroll
            for (int k = 0; k < 16; k++) {
                if (flags & (1u << k)) scnt[pos++] = base + (unsigned)k;
            }
            __syncthreads();

            // ---- masked argmax over compacted counters ----
            unsigned bv = 0u;
            unsigned bc = rowbase + (unsigned)(HW - 1);  // phantom: loses always

            int t = tid;
            for (; t + 256 < m; t += 512) {      // two independent chains
                unsigned c0 = scnt[t];
                unsigned c1 = scnt[t + 256];
                unsigned v0 = threefry_bits(c0);
                unsigned v1 = threefry_bits(c1);
                if (v0 > bv) { bv = v0; bc = c0; }   // c0 < c1: order preserved
                if (v1 > bv) { bv = v1; bc = c1; }
            }
            if (t < m) {
                unsigned c = scnt[t];
                unsigned v = threefry_bits(c);
                if (v > bv) { bv = v; bc = c; }
            }

            const int bj = (int)(bc - rowbase);
            unsigned long long key =
                ((unsigned long long)bv << 12) | (unsigned)(HW - 1 - bj);
#pragma unroll
            for (int o = 16; o > 0; o >>= 1) {
                unsigned long long other = __shfl_xor_sync(0xFFFFFFFFu, key, o);
                if (other > key) key = other;
            }
            if ((tid & 31) == 0) wmax[tid >> 5] = key;
            __syncthreads();
            if (tid < 32) {
                unsigned long long k2 = (tid < 8) ? wmax[tid] : 0ull;
#pragma unroll
                for (int o = 4; o > 0; o >>= 1) {
                    unsigned long long other = __shfl_xor_sync(0xFFFFFFFFu, k2, o);
                    if (other > k2) k2 = other;
                }
                if (tid == 0) {
                    g_sidx[row] = (m == 0) ? 0 : (HW - 1 - (int)(k2 & 0xFFFu));
                    __threadfence();
                    atomicAdd(&g_done, 1);     // publish early, before the copy
                }
            }
        } else {
            // dead row: nb never consumed
            if (tid == 0) {
                g_sidx[row] = -1;
                __threadfence();
                atomicAdd(&g_done, 1);
            }
        }

        // ================= phase 2: copy plane = bid =================
        const int b  = bid >> 9;             // /512
        const int ch = bid & 511;
        const float4* __restrict__ src =
            (const float4*)(x + ((size_t)b * CIN + ch) * HW);
        float4* __restrict__ dst =
            (float4*)(out + ((size_t)b * COUT + ch) * HW);
#pragma unroll
        for (int k = 0; k < 4; k++) {
            int idx = tid + k * 256;
            dst[idx] = src[idx];
        }
    } else {
        // ================= shift CTA =================
        const int p  = bid - N_MERGED;       // 0..2047
        const int b  = p >> 8;
        const int cc = p & 255;

        if (tid == 0) {
            // spin until every merged CTA has published its g_sidx entry.
            while (atomicAdd(&g_done, 0) != N_MERGED) __nanosleep(200);
            // the LAST shift CTA to pass the spin resets counters for the
            // next graph replay (all others already observed the condition).
            int a = atomicAdd(&g_arrived, 1);
            if (a == N_SHIFT - 1) {
                atomicExch(&g_done, 0);
                atomicExch(&g_arrived, 0);
            }
        }
        __syncthreads();

        const float* __restrict__ src = x + ((size_t)b * CIN + C2 + cc) * HW;
        float4* __restrict__ dst =
            (float4*)(out + ((size_t)b * COUT + CIN + cc) * HW);
        const int4* __restrict__ sidx4 = (const int4*)g_sidx;
#pragma unroll
        for (int k = 0; k < 4; k++) {
            int idx = tid + k * 256;
            int4 s = sidx4[idx];
            float4 v;
            v.x = (s.x >= 0) ? __ldg(src + s.x) : 0.0f;
            v.y = (s.y >= 0) ? __ldg(src + s.y) : 0.0f;
            v.z = (s.z >= 0) ? __ldg(src + s.z) : 0.0f;
            v.w = (s.w >= 0) ? __ldg(src + s.w) : 0.0f;
            dst[idx] = v;
        }
    }
}

// ---------------------------------------------------------------------------
extern "C" void kernel_launch(void* const* d_in, const int* in_sizes, int n_in,
                              void* d_out, int out_size) {
    const float* x    = (const float*)d_in[0];   // (8,512,64,64) f32
    const int*   mask = (const int*)d_in[1];     // (64,64) i32
    float* out = (float*)d_out;                  // (8,768,64,64) f32
    (void)in_sizes; (void)n_in; (void)out_size;

    fused_kernel<<<GRID_TOTAL, 256>>>(x, mask, out);
}